// round 13
// baseline (speedup 1.0000x reference)
#include <cuda_runtime.h>
#include <cstdint>

// MC3DAD kNN(k=5) curvature. B=8, N=4096, D=3.
// Register-tiled: each thread handles T=4 points x 1/8 slice of candidates.
// Two-pass: (1) branch-free group-min bound on rank proxy r = sq_j - 2*dot,
// merged across slice lanes; (2) rescan with constant per-point thresholds,
// rare exact u64-key (clamped-d2, index) inserts == jax top_k ordering.

#define NPTS 4096
#define NBATCH 8
#define TPB 128
#define SPLIT 8
#define TILE 4
#define PPB (TPB / SPLIT * TILE)      // 64 points per block
#define SLICE (NPTS / 2 / SPLIT)      // 256 pair-entries per thread slice

#define SENT_KEY ((((unsigned long long)0x7f800000u) << 32) | 0xFFFFFFFFu)
#define F_INF __int_as_float(0x7f800000)

// ---------------- packed f32x2 helpers (Blackwell) ----------------
__device__ __forceinline__ unsigned long long f32x2_mul(unsigned long long a, unsigned long long b) {
    unsigned long long r;
    asm("mul.rn.f32x2 %0, %1, %2;" : "=l"(r) : "l"(a), "l"(b));
    return r;
}
__device__ __forceinline__ unsigned long long f32x2_add(unsigned long long a, unsigned long long b) {
    unsigned long long r;
    asm("add.rn.f32x2 %0, %1, %2;" : "=l"(r) : "l"(a), "l"(b));
    return r;
}
__device__ __forceinline__ unsigned long long f32x2_fma(unsigned long long a, unsigned long long b, unsigned long long c) {
    unsigned long long r;
    asm("fma.rn.f32x2 %0, %1, %2, %3;" : "=l"(r) : "l"(a), "l"(b), "l"(c));
    return r;
}
__device__ __forceinline__ unsigned long long pk2(float lo, float hi) {
    unsigned long long r;
    asm("mov.b64 %0, {%1, %2};" : "=l"(r) : "f"(lo), "f"(hi));
    return r;
}
__device__ __forceinline__ void up2(unsigned long long v, float& lo, float& hi) {
    asm("mov.b64 {%0, %1}, %2;" : "=f"(lo), "=f"(hi) : "l"(v));
}

// Branch-free insert of v into ascending 5-list s[0..4] (values only).
__device__ __forceinline__ void vins5(float* s, float v) {
    s[4] = fminf(s[4], fmaxf(s[3], v));
    s[3] = fminf(s[3], fmaxf(s[2], v));
    s[2] = fminf(s[2], fmaxf(s[1], v));
    s[1] = fminf(s[1], fmaxf(s[0], v));
    s[0] = fminf(s[0], v);
}

// Insert u64 key into sorted k[0]<=..<=k[4], dropping largest.
__device__ __forceinline__ void kins5(unsigned long long* k, unsigned long long key) {
    if (key < k[4]) {
        k[4] = key;
        if (k[4] < k[3]) { unsigned long long t = k[3]; k[3] = k[4]; k[4] = t; }
        if (k[3] < k[2]) { unsigned long long t = k[2]; k[2] = k[3]; k[3] = t; }
        if (k[2] < k[1]) { unsigned long long t = k[1]; k[1] = k[2]; k[2] = t; }
        if (k[1] < k[0]) { unsigned long long t = k[0]; k[0] = k[1]; k[1] = t; }
    }
}

__global__ __launch_bounds__(TPB, 3) void geom_kernel(const float* __restrict__ pcd,
                                                      float* __restrict__ out) {
    // smem: Af[p*4+{0,1}]=x pair, Af[p*4+{2,3}]=y pair;
    //       Bf[p*4+{0,1}]=z pair, Bf[p*4+{2,3}]=|p|^2 pair.
    extern __shared__ float sm[];
    float* Af = sm;
    float* Bf = sm + NPTS * 2;

    const int b = blockIdx.y;
    const float* __restrict__ P = pcd + (size_t)b * NPTS * 3;

    for (int j = threadIdx.x; j < NPTS; j += TPB) {
        float x = P[3 * j + 0];
        float y = P[3 * j + 1];
        float z = P[3 * j + 2];
        // unfused, mirrors jnp.sum(pcd*pcd, -1)
        float sq = __fadd_rn(__fadd_rn(__fmul_rn(x, x), __fmul_rn(y, y)), __fmul_rn(z, z));
        int p = j >> 1, l = j & 1;
        Af[p * 4 + l]     = x;
        Af[p * 4 + 2 + l] = y;
        Bf[p * 4 + l]     = z;
        Bf[p * 4 + 2 + l] = sq;
    }
    __syncthreads();

    const int s  = threadIdx.x & (SPLIT - 1);       // slice lane 0..7
    const int pg = threadIdx.x >> 3;                // point-group 0..15
    const int i0 = blockIdx.x * PPB + pg * TILE;    // first of this thread's 4 points

    // Per-point packed constants.
    unsigned long long xq[TILE], yq[TILE], zq[TILE], sq2[TILE];
#pragma unroll
    for (int pt = 0; pt < TILE; ++pt) {
        const int i = i0 + pt;
        float xi = P[3 * i + 0];
        float yi = P[3 * i + 1];
        float zi = P[3 * i + 2];
        float sqi = __fadd_rn(__fadd_rn(__fmul_rn(xi, xi), __fmul_rn(yi, yi)),
                              __fmul_rn(zi, zi));
        xq[pt]  = pk2(xi, xi);
        yq[pt]  = pk2(yi, yi);
        zq[pt]  = pk2(zi, zi);
        sq2[pt] = pk2(sqi, sqi);
    }
    const unsigned long long n22 = pk2(-2.0f, -2.0f);

    const ulonglong2* __restrict__ A8 = (const ulonglong2*)Af;
    const ulonglong2* __restrict__ B8 = (const ulonglong2*)Bf;

    // ---------- Pass 1: group-mins of r = sq_j - 2*dot (2 groups/side) ------
    float gA[TILE][2], gB[TILE][2];
#pragma unroll
    for (int pt = 0; pt < TILE; ++pt) {
        gA[pt][0] = F_INF; gA[pt][1] = F_INF;
        gB[pt][0] = F_INF; gB[pt][1] = F_INF;
    }

#pragma unroll 4
    for (int t = 0; t < SLICE; ++t) {
        const int p = (t << 3) + s;
        ulonglong2 av = A8[p];
        ulonglong2 cv = B8[p];
        const int grp = t & 1;  // static under unroll
#pragma unroll
        for (int pt = 0; pt < TILE; ++pt) {
            unsigned long long m = f32x2_mul(xq[pt], av.x);
            m = f32x2_fma(yq[pt], av.y, m);
            m = f32x2_fma(zq[pt], cv.x, m);
            unsigned long long r2 = f32x2_fma(n22, m, cv.y);
            float rlo, rhi;
            up2(r2, rlo, rhi);
            gA[pt][grp] = fminf(gA[pt][grp], rlo);
            gB[pt][grp] = fminf(gB[pt][grp], rhi);
        }
    }

    // Per point: 5 smallest of (8 lanes x 4 groups) = 32 disjoint group mins.
    // s5[pt][4] then bounds the true 5th-NN rank proxy (5 distinct cands <= it).
    float wq[TILE];
#pragma unroll
    for (int pt = 0; pt < TILE; ++pt) {
        float sl[5] = {F_INF, F_INF, F_INF, F_INF, F_INF};
        vins5(sl, gA[pt][0]); vins5(sl, gA[pt][1]);
        vins5(sl, gB[pt][0]); vins5(sl, gB[pt][1]);
#pragma unroll
        for (int mask = 1; mask <= 4; mask <<= 1) {
            float o0 = __shfl_xor_sync(0xFFFFFFFFu, sl[0], mask);
            float o1 = __shfl_xor_sync(0xFFFFFFFFu, sl[1], mask);
            float o2 = __shfl_xor_sync(0xFFFFFFFFu, sl[2], mask);
            float o3 = __shfl_xor_sync(0xFFFFFFFFu, sl[3], mask);
            float o4 = __shfl_xor_sync(0xFFFFFFFFu, sl[4], mask);
            vins5(sl, o0); vins5(sl, o1); vins5(sl, o2); vins5(sl, o3); vins5(sl, o4);
        }
        // ulp padding: r-ordering vs exact-d2 ordering differ by rounding only;
        // keep a superset (false positives resolved exactly by u64 keys).
        wq[pt] = sl[4] + fabsf(sl[4]) * 4e-6f + 1e-33f;
    }

    // ---------- Pass 2: rescan slice, rare exact inserts --------------------
    unsigned long long K[TILE][5];
#pragma unroll
    for (int pt = 0; pt < TILE; ++pt)
#pragma unroll
        for (int q = 0; q < 5; ++q) K[pt][q] = SENT_KEY;

#pragma unroll 4
    for (int t = 0; t < SLICE; ++t) {
        const int p = (t << 3) + s;
        ulonglong2 av = A8[p];
        ulonglong2 cv = B8[p];
#pragma unroll
        for (int pt = 0; pt < TILE; ++pt) {
            unsigned long long m = f32x2_mul(xq[pt], av.x);
            m = f32x2_fma(yq[pt], av.y, m);
            m = f32x2_fma(zq[pt], cv.x, m);
            unsigned long long r2 = f32x2_fma(n22, m, cv.y);
            float rlo, rhi;
            up2(r2, rlo, rhi);
            if (fminf(rlo, rhi) <= wq[pt]) {
                // exact reference-rounded d2 = fma(-2, dot, RN(sq_i + sq_j))
                unsigned long long base = f32x2_add(sq2[pt], cv.y);
                unsigned long long d2p  = f32x2_fma(n22, m, base);
                float dlo, dhi;
                up2(d2p, dlo, dhi);
                int j = 2 * p;
                if (rlo <= wq[pt]) {
                    float dc = fmaxf(dlo, 0.0f);
                    kins5(K[pt], ((unsigned long long)__float_as_uint(dc) << 32) | (unsigned)j);
                }
                if (rhi <= wq[pt]) {
                    float dc = fmaxf(dhi, 0.0f);
                    kins5(K[pt], ((unsigned long long)__float_as_uint(dc) << 32) | (unsigned)(j + 1));
                }
            }
        }
    }

    // Merge exact top-5 key lists across the 8 slice lanes (keys unique).
#pragma unroll
    for (int pt = 0; pt < TILE; ++pt) {
#pragma unroll
        for (int mask = 1; mask <= 4; mask <<= 1) {
            unsigned long long o0 = __shfl_xor_sync(0xFFFFFFFFu, K[pt][0], mask);
            unsigned long long o1 = __shfl_xor_sync(0xFFFFFFFFu, K[pt][1], mask);
            unsigned long long o2 = __shfl_xor_sync(0xFFFFFFFFu, K[pt][2], mask);
            unsigned long long o3 = __shfl_xor_sync(0xFFFFFFFFu, K[pt][3], mask);
            unsigned long long o4 = __shfl_xor_sync(0xFFFFFFFFu, K[pt][4], mask);
            kins5(K[pt], o0); kins5(K[pt], o1); kins5(K[pt], o2);
            kins5(K[pt], o3); kins5(K[pt], o4);
        }
    }

    // ---------- Epilogue (lane s==0 of each point-group) --------------------
    if (s == 0) {
#pragma unroll
        for (int pt = 0; pt < TILE; ++pt) {
            float px[5], py[5], pz[5];
            float sx = 0.0f, sy = 0.0f, sz = 0.0f;
#pragma unroll
            for (int q = 0; q < 5; ++q) {
                unsigned j = (unsigned)K[pt][q] & (NPTS - 1);  // hard OOB guard
                int p = j >> 1, l = j & 1;
                float ax0 = Af[p * 4 + 0], ax1 = Af[p * 4 + 1];
                float ay0 = Af[p * 4 + 2], ay1 = Af[p * 4 + 3];
                float az0 = Bf[p * 4 + 0], az1 = Bf[p * 4 + 1];
                px[q] = l ? ax1 : ax0;
                py[q] = l ? ay1 : ay0;
                pz[q] = l ? az1 : az0;
                sx += px[q]; sy += py[q]; sz += pz[q];
            }
            float cx = sx / 5.0f, cy = sy / 5.0f, cz = sz / 5.0f;
            float tr = 0.0f;
#pragma unroll
            for (int q = 0; q < 5; ++q) {
                float dx = px[q] - cx, dy = py[q] - cy, dz = pz[q] - cz;
                tr += dx * dx + dy * dy + dz * dz;
            }
            out[b * NPTS + i0 + pt] = tr * 0.25f;  // / (k - 1)
        }
    }
}

// Per-batch normalization: curvature = trace / (sum(trace) + 1e-8).
__global__ __launch_bounds__(512) void norm_kernel(float* __restrict__ out) {
    __shared__ float red[16];
    const int b = blockIdx.x;
    const int t = threadIdx.x;
    float v[NPTS / 512];
    float s = 0.0f;
#pragma unroll
    for (int q = 0; q < NPTS / 512; ++q) {
        v[q] = out[b * NPTS + q * 512 + t];
        s += v[q];
    }
#pragma unroll
    for (int o = 16; o > 0; o >>= 1)
        s += __shfl_xor_sync(0xFFFFFFFFu, s, o);
    if ((t & 31) == 0) red[t >> 5] = s;
    __syncthreads();
    float tot = 0.0f;
#pragma unroll
    for (int wgt = 0; wgt < 16; ++wgt) tot += red[wgt];
    float denom = tot + 1e-8f;
#pragma unroll
    for (int q = 0; q < NPTS / 512; ++q) {
        out[b * NPTS + q * 512 + t] = v[q] / denom;
    }
}

extern "C" void kernel_launch(void* const* d_in, const int* in_sizes, int n_in,
                              void* d_out, int out_size) {
    const float* pcd = (const float*)d_in[0];  // [8, 4096, 3] f32
    float* out = (float*)d_out;                // [8, 4096] f32

    cudaFuncSetAttribute(geom_kernel, cudaFuncAttributeMaxDynamicSharedMemorySize, 65536);

    dim3 grid(NPTS / PPB, NBATCH);  // (64, 8) = 512 blocks of 128 threads
    geom_kernel<<<grid, TPB, 65536>>>(pcd, out);
    norm_kernel<<<NBATCH, 512>>>(out);
}